// round 6
// baseline (speedup 1.0000x reference)
#include <cuda_runtime.h>
#include <math.h>

// Shape fixed by dataset: B=16, N=1024, E=128, kv row = 2E+1 = 257
#define BATCH   16
#define NATOMS  1024
#define EDIM    128
#define KVROW   257
#define TI      128
#define TJ      128
#define THREADS 512

// SMEM layout (floats):
//  sK : [128 ksteps][128 dup-pairs]  (k_i, k_i) f32x2, row = 256 floats (1024B)
//  sV : [128 ksteps][64 pairs]       (v_p, v_{p+64}) f32x2, row = 128 floats (512B)
//  sPn: negated j-tile positions  x[0,128) y[128,256) z[256,384)
//  sPi: dup'd i positions: float offset i*6 + axis*2
//  sMS: 16 warp partials for mask sum
//  (final cross-warp reduce buffer overlays sV after the main loop)
#define OFF_SV  (EDIM * 256)            // 32768
#define OFF_PN  (OFF_SV + EDIM * 128)   // 49152
#define OFF_PI  (OFF_PN + 3 * TJ)       // 49536
#define OFF_MS  (OFF_PI + TI * 6)       // 50304
#define SMEM_FLOATS (OFF_MS + 16)       // 50320 floats = 201.28 KB
#define SMEM_BYTES  (SMEM_FLOATS * sizeof(float))

typedef unsigned long long ull;

__device__ __forceinline__ ull pk2(float lo, float hi) {
    ull r; asm("mov.b64 %0, {%1, %2};" : "=l"(r) : "f"(lo), "f"(hi)); return r;
}
__device__ __forceinline__ void upk2(ull v, float& lo, float& hi) {
    asm("mov.b64 {%0, %1}, %2;" : "=f"(lo), "=f"(hi) : "l"(v));
}
__device__ __forceinline__ ull fma2(ull a, ull b, ull c) {
    ull d; asm("fma.rn.f32x2 %0, %1, %2, %3;" : "=l"(d) : "l"(a), "l"(b), "l"(c)); return d;
}
__device__ __forceinline__ ull add2(ull a, ull b) {
    ull d; asm("add.rn.f32x2 %0, %1, %2;" : "=l"(d) : "l"(a), "l"(b)); return d;
}
__device__ __forceinline__ ull mul2(ull a, ull b) {
    ull d; asm("mul.rn.f32x2 %0, %1, %2;" : "=l"(d) : "l"(a), "l"(b)); return d;
}

__global__ __launch_bounds__(THREADS, 1)
void gen_actions_kernel(const float* __restrict__ kv,
                        const float* __restrict__ pos,
                        const float* __restrict__ mask,
                        const float* __restrict__ ascale,
                        float* __restrict__ out)
{
    extern __shared__ float sm[];
    float* sK  = sm;
    float* sV  = sm + OFF_SV;
    float* sPn = sm + OFF_PN;
    float* sPi = sm + OFF_PI;
    float* sMS = sm + OFF_MS;

    const int tid  = threadIdx.x;
    const int w    = tid >> 5;
    const int lane = tid & 31;
    const int wy   = w & 3;         // row warp-group: rows [32*wy, 32*wy+32)
    const int wxg  = w >> 2;        // col warp-group: pairs [16*wxg, 16*wxg+16)
    const int ry   = lane & 7;      // 8 row subgroups within warp
    const int cx   = lane >> 3;     // 4 col subgroups within warp
    const int rbase = 32 * wy + 4 * ry;   // this thread's 4 contiguous rows
    const int pbase = 16 * wxg + 4 * cx;  // this thread's 4 contiguous pairs

    const int b  = blockIdx.y;
    const int i0 = blockIdx.x * TI;

    const float* kvb = kv   + (size_t)b * NATOMS * KVROW;
    const float* mb  = mask + (size_t)b * NATOMS;
    const float* pb  = pos  + (size_t)b * NATOMS * 3;

    const float inv_sqrt_e = 0.088388347648318447f;  // 1/sqrt(128)

    // ---- K tile: dup-packed (k,k) f32x2, mask*invsqrtE folded ----
    for (int idx = tid; idx < TI * EDIM; idx += THREADS) {
        int i = idx >> 7;
        int e = idx & (EDIM - 1);
        float v = kvb[(size_t)(i0 + i) * KVROW + e] * (mb[i0 + i] * inv_sqrt_e);
        *(ull*)&sK[e * 256 + 2 * i] = pk2(v, v);
    }

    // ---- i positions, dup-packed once per block ----
    if (tid < TI) {
        const float* p = pb + (size_t)(i0 + tid) * 3;
        *(ull*)&sPi[tid * 6 + 0] = pk2(p[0], p[0]);
        *(ull*)&sPi[tid * 6 + 2] = pk2(p[1], p[1]);
        *(ull*)&sPi[tid * 6 + 4] = pk2(p[2], p[2]);
    }

    // ---- mask sum ----
    {
        float ms = 0.f;
        for (int n = tid; n < NATOMS; n += THREADS) ms += mb[n];
        #pragma unroll
        for (int off = 16; off > 0; off >>= 1)
            ms += __shfl_xor_sync(0xFFFFFFFFu, ms, off);
        if (lane == 0) sMS[w] = ms;
    }
    __syncthreads();

    float msum = 0.f;
    #pragma unroll
    for (int q = 0; q < THREADS / 32; q++) msum += sMS[q];
    const float inv_msum = 1.0f / msum;
    const float as = ascale[0];

    // packed accumulators over this thread's 4 rows (pair lanes folded later)
    ull accx[4], accy[4], accz[4];
    #pragma unroll
    for (int r = 0; r < 4; r++) { accx[r] = 0ULL; accy[r] = 0ULL; accz[r] = 0ULL; }

    for (int jt = 0; jt < NATOMS; jt += TJ) {
        __syncthreads();   // prior tile fully consumed

        // V tile: packed pairs (p, p+64); gmem coalesced; mask folded.
        for (int idx = tid; idx < TJ * EDIM; idx += THREADS) {
            int j = idx >> 7;
            int e = idx & (EDIM - 1);
            float v = kvb[(size_t)(jt + j) * KVROW + EDIM + e] * mb[jt + j];
            sV[e * 128 + 2 * (j & 63) + (j >> 6)] = v;
        }
        if (tid < TJ) {
            const float* p = pb + (size_t)(jt + tid) * 3;
            sPn[tid] = -p[0]; sPn[TJ + tid] = -p[1]; sPn[2 * TJ + tid] = -p[2];
        }
        __syncthreads();

        // packed negated column positions for this thread's 4 pairs
        ull nqx[4], nqy[4], nqz[4];
        #pragma unroll
        for (int c = 0; c < 4; c++) {
            int p = pbase + c;
            nqx[c] = pk2(sPn[p],          sPn[p + 64]);
            nqy[c] = pk2(sPn[TJ + p],     sPn[TJ + p + 64]);
            nqz[c] = pk2(sPn[2 * TJ + p], sPn[2 * TJ + p + 64]);
        }

        // ---- packed GEMM: 4 rows x 4 pairs, all LDS.128, conflict-free ----
        ull S[4][4];
        #pragma unroll
        for (int r = 0; r < 4; r++)
            #pragma unroll
            for (int c = 0; c < 4; c++) S[r][c] = 0ULL;

        #pragma unroll 4
        for (int ks = 0; ks < EDIM; ks++) {
            const float* kr = sK + ks * 256;
            const float* vr = sV + ks * 128;
            ulonglong2 k01 = *(const ulonglong2*)&kr[2 * rbase];      // rows r,r+1
            ulonglong2 k23 = *(const ulonglong2*)&kr[2 * rbase + 4];  // rows r+2,r+3
            ulonglong2 v01 = *(const ulonglong2*)&vr[2 * pbase];      // pairs c,c+1
            ulonglong2 v23 = *(const ulonglong2*)&vr[2 * pbase + 4];  // pairs c+2,c+3
            ull kf[4] = { k01.x, k01.y, k23.x, k23.y };
            ull vf[4] = { v01.x, v01.y, v23.x, v23.y };
            #pragma unroll
            for (int r = 0; r < 4; r++)
                #pragma unroll
                for (int c = 0; c < 4; c++)
                    S[r][c] = fma2(kf[r], vf[c], S[r][c]);
        }

        // ---- fused packed epilogue ----
        #pragma unroll
        for (int r = 0; r < 4; r++) {
            int ii = rbase + r;
            ull pix2 = *(const ull*)&sPi[ii * 6 + 0];
            ull piy2 = *(const ull*)&sPi[ii * 6 + 2];
            ull piz2 = *(const ull*)&sPi[ii * 6 + 4];
            #pragma unroll
            for (int c = 0; c < 4; c++) {
                ull dx2 = add2(pix2, nqx[c]);
                ull dy2 = add2(piy2, nqy[c]);
                ull dz2 = add2(piz2, nqz[c]);
                ull d2  = mul2(dz2, dz2);
                d2 = fma2(dy2, dy2, d2);
                d2 = fma2(dx2, dx2, d2);
                float dlo, dhi;
                upk2(d2, dlo, dhi);
                // diagonal (d2==0): clamp -> huge finite inv, dx==0 -> 0
                float ilo = rsqrtf(fmaxf(dlo, 1e-36f));
                float ihi = rsqrtf(fmaxf(dhi, 1e-36f));
                ull w2 = mul2(S[r][c], pk2(ilo, ihi));
                accx[r] = fma2(w2, dx2, accx[r]);
                accy[r] = fma2(w2, dy2, accy[r]);
                accz[r] = fma2(w2, dz2, accz[r]);
            }
        }
    }

    // ---- reduction ----
    // 1) fold packed pair lanes
    float ax[4], ay[4], az[4];
    #pragma unroll
    for (int r = 0; r < 4; r++) {
        float lo, hi;
        upk2(accx[r], lo, hi); ax[r] = lo + hi;
        upk2(accy[r], lo, hi); ay[r] = lo + hi;
        upk2(accz[r], lo, hi); az[r] = lo + hi;
    }
    // 2) reduce over cx within the warp (lanes differ in bits 3,4)
    #pragma unroll
    for (int off = 8; off <= 16; off <<= 1) {
        #pragma unroll
        for (int r = 0; r < 4; r++) {
            ax[r] += __shfl_xor_sync(0xFFFFFFFFu, ax[r], off);
            ay[r] += __shfl_xor_sync(0xFFFFFFFFu, ay[r], off);
            az[r] += __shfl_xor_sync(0xFFFFFFFFu, az[r], off);
        }
    }
    // 3) cross warp-group (wxg) partials staged in smem (reuse sV region)
    __syncthreads();                 // everyone done reading sV
    float* sRd = sV;                 // [4 wxg][128 rows][3 axes]
    if (cx == 0) {
        #pragma unroll
        for (int r = 0; r < 4; r++) {
            int row = rbase + r;
            float* d = sRd + (wxg * 128 + row) * 3;
            d[0] = ax[r]; d[1] = ay[r]; d[2] = az[r];
        }
    }
    __syncthreads();

    if (tid < TI) {
        int gi = i0 + tid;
        float sx = 0.f, sy = 0.f, sz = 0.f;
        #pragma unroll
        for (int g = 0; g < 4; g++) {
            const float* d = sRd + (g * 128 + tid) * 3;
            sx += d[0]; sy += d[1]; sz += d[2];
        }
        float s = as * mb[gi];
        float* o = out + ((size_t)b * NATOMS + gi) * 3;
        o[0] = tanhf(sx * inv_msum) * s;
        o[1] = tanhf(sy * inv_msum) * s;
        o[2] = tanhf(sz * inv_msum) * s;
    }
}

extern "C" void kernel_launch(void* const* d_in, const int* in_sizes, int n_in,
                              void* d_out, int out_size) {
    const float* kv   = (const float*)d_in[0];
    const float* pos  = (const float*)d_in[1];
    const float* mask = (const float*)d_in[2];
    const float* asc  = (const float*)d_in[3];
    float* out = (float*)d_out;

    cudaFuncSetAttribute(gen_actions_kernel,
                         cudaFuncAttributeMaxDynamicSharedMemorySize,
                         (int)SMEM_BYTES);

    dim3 grid(NATOMS / TI, BATCH);   // 8 x 16 = 128 blocks, one wave
    gen_actions_kernel<<<grid, THREADS, SMEM_BYTES>>>(kv, pos, mask, asc, out);
}

// round 8
// speedup vs baseline: 4.0128x; 4.0128x over previous
#include <cuda_runtime.h>
#include <cuda_bf16.h>
#include <math.h>
#include <cstdint>

// Shape fixed by dataset: B=16, N=1024, E=128, kv row = 2E+1 = 257
#define BATCH   16
#define NATOMS  1024
#define EDIM    128
#define KVROW   257
#define TI      128
#define TJ      128
#define THREADS 512

// bf16 tile rows padded to 136 elems (272 B): ldmatrix row offsets mod 128B
// cycle through {0,16,...,112} -> conflict-free without swizzle.
#define STRIDE_B   272
#define TILE_BYTES (128 * STRIDE_B)          // 34816
#define OFF_AHI 0
#define OFF_ALO (OFF_AHI + TILE_BYTES)
#define OFF_BHI (OFF_ALO + TILE_BYTES)
#define OFF_BLO (OFF_BHI + TILE_BYTES)
#define OFF_PN  (OFF_BLO + TILE_BYTES)       // negated j pos: 3*128 floats
#define OFF_RED (OFF_PN + 1536)              // 4 col-groups * 128 rows * 3 floats
#define OFF_MS  (OFF_RED + 6144)             // 16 floats
#define SMEM_BYTES (OFF_MS + 64 + 256)       // ~147.2 KB

__device__ __forceinline__ uint32_t smem_u32(const void* p) {
    uint32_t a;
    asm("{ .reg .u64 t; cvta.to.shared.u64 t, %1; cvt.u32.u64 %0, t; }"
        : "=r"(a) : "l"(p));
    return a;
}

#define LDSM4(r, addr)                                                      \
    asm volatile("ldmatrix.sync.aligned.m8n8.x4.shared.b16 {%0,%1,%2,%3}, [%4];" \
        : "=r"((r)[0]), "=r"((r)[1]), "=r"((r)[2]), "=r"((r)[3]) : "r"(addr))

#define MMA_BF16(c, a, b0_, b1_)                                            \
    asm volatile("mma.sync.aligned.m16n8k16.row.col.f32.bf16.bf16.f32 "     \
        "{%0,%1,%2,%3}, {%4,%5,%6,%7}, {%8,%9}, {%0,%1,%2,%3};"             \
        : "+f"((c)[0]), "+f"((c)[1]), "+f"((c)[2]), "+f"((c)[3])            \
        : "r"((a)[0]), "r"((a)[1]), "r"((a)[2]), "r"((a)[3]),               \
          "r"(b0_), "r"(b1_))

// split fp32 pair into packed bf16 hi + bf16 lo (x ~= hi + lo)
__device__ __forceinline__ void split_pair(float v0, float v1,
                                           uint32_t& hi, uint32_t& lo) {
    __nv_bfloat16 h0 = __float2bfloat16(v0);
    __nv_bfloat16 h1 = __float2bfloat16(v1);
    __nv_bfloat16 l0 = __float2bfloat16(v0 - __bfloat162float(h0));
    __nv_bfloat16 l1 = __float2bfloat16(v1 - __bfloat162float(h1));
    hi = (uint32_t)__bfloat16_as_ushort(h0) | ((uint32_t)__bfloat16_as_ushort(h1) << 16);
    lo = (uint32_t)__bfloat16_as_ushort(l0) | ((uint32_t)__bfloat16_as_ushort(l1) << 16);
}

__global__ __launch_bounds__(THREADS, 1)
void gen_actions_kernel(const float* __restrict__ kv,
                        const float* __restrict__ pos,
                        const float* __restrict__ mask,
                        const float* __restrict__ ascale,
                        float* __restrict__ out)
{
    extern __shared__ char sp[];
    const uint32_t sb = smem_u32(sp);

    const int tid  = threadIdx.x;
    const int wid  = tid >> 5;
    const int lane = tid & 31;
    const int wr   = wid & 3;       // warp row: S rows [32wr, 32wr+32)
    const int wc   = wid >> 2;      // warp col: S cols [32wc, 32wc+32)
    const int qid  = lane >> 2;     // quad id (fragment row group)
    const int qe   = lane & 3;      // fragment column pair

    const int b  = blockIdx.y;
    const int i0 = blockIdx.x * TI;

    const float* kvb = kv   + (size_t)b * NATOMS * KVROW;
    const float* mb  = mask + (size_t)b * NATOMS;
    const float* pb  = pos  + (size_t)b * NATOMS * 3;

    const float inv_sqrt_e = 0.088388347648318447f;  // 1/sqrt(128)

    // ---- K tile: bf16 hi/lo split, mask*invsqrtE folded ----
    for (int idx = tid; idx < TI * 64; idx += THREADS) {
        int r = idx >> 6;                 // row 0..127
        int p = idx & 63;                 // pair 0..63 -> e = 2p, 2p+1
        float m = mb[i0 + r] * inv_sqrt_e;
        const float* g = kvb + (size_t)(i0 + r) * KVROW + 2 * p;
        uint32_t hi, lo;
        split_pair(g[0] * m, g[1] * m, hi, lo);
        *(uint32_t*)(sp + OFF_AHI + r * STRIDE_B + 4 * p) = hi;
        *(uint32_t*)(sp + OFF_ALO + r * STRIDE_B + 4 * p) = lo;
    }

    // ---- mask sum ----
    {
        float* sMS = (float*)(sp + OFF_MS);
        float ms = 0.f;
        for (int n = tid; n < NATOMS; n += THREADS) ms += mb[n];
        #pragma unroll
        for (int off = 16; off > 0; off >>= 1)
            ms += __shfl_xor_sync(0xFFFFFFFFu, ms, off);
        if (lane == 0) sMS[wid] = ms;
    }
    __syncthreads();
    float msum = 0.f;
    {
        float* sMS = (float*)(sp + OFF_MS);
        #pragma unroll
        for (int q = 0; q < 16; q++) msum += sMS[q];
    }
    const float inv_msum = 1.0f / msum;
    const float as = ascale[0];

    // ---- this thread's 4 fixed rows: 32wr + 16mt + 8h + qid ----
    float pix[4], piy[4], piz[4];
    #pragma unroll
    for (int mt = 0; mt < 2; mt++)
        #pragma unroll
        for (int h = 0; h < 2; h++) {
            int gi = i0 + 32 * wr + 16 * mt + 8 * h + qid;
            const float* p = pb + (size_t)gi * 3;
            pix[2 * mt + h] = p[0]; piy[2 * mt + h] = p[1]; piz[2 * mt + h] = p[2];
        }

    // ---- ldmatrix lane base addresses (conflict-free, see STRIDE_B note) ----
    // A x4: lanes 0-7 rows m0..7 @k0 | 8-15 rows m8..15 @k0
    //     | 16-23 rows m0..7 @k+8 | 24-31 rows m8..15 @k+8
    const uint32_t aRow = 32 * wr + (lane & 15);
    const uint32_t aKof = (lane & 16) ? 16u : 0u;
    const uint32_t aHiB = sb + OFF_AHI + aRow * STRIDE_B + aKof;
    const uint32_t aLoB = sb + OFF_ALO + aRow * STRIDE_B + aKof;
    // B x4: lanes 0-7 rows n0..7 @k0 | 8-15 rows n0..7 @k+8
    //     | 16-23 rows n8..15 @k0 | 24-31 rows n8..15 @k+8
    const uint32_t bRow = 32 * wc + (lane & 7) + ((lane & 16) ? 8 : 0);
    const uint32_t bKof = (lane & 8) ? 16u : 0u;
    const uint32_t bHiB = sb + OFF_BHI + bRow * STRIDE_B + bKof;
    const uint32_t bLoB = sb + OFF_BLO + bRow * STRIDE_B + bKof;

    float* sPnx = (float*)(sp + OFF_PN);
    float* sPny = sPnx + 128;
    float* sPnz = sPnx + 256;

    float ax[4], ay[4], az[4];
    #pragma unroll
    for (int r = 0; r < 4; r++) { ax[r] = 0.f; ay[r] = 0.f; az[r] = 0.f; }

    for (int jt = 0; jt < NATOMS; jt += TJ) {
        __syncthreads();   // prev tile's ldsm + sPn reads complete

        // ---- V tile: bf16 hi/lo split, mask folded ----
        for (int idx = tid; idx < TJ * 64; idx += THREADS) {
            int r = idx >> 6;
            int p = idx & 63;
            float m = mb[jt + r];
            const float* g = kvb + (size_t)(jt + r) * KVROW + EDIM + 2 * p;
            uint32_t hi, lo;
            split_pair(g[0] * m, g[1] * m, hi, lo);
            *(uint32_t*)(sp + OFF_BHI + r * STRIDE_B + 4 * p) = hi;
            *(uint32_t*)(sp + OFF_BLO + r * STRIDE_B + 4 * p) = lo;
        }
        if (tid < TJ) {
            const float* p = pb + (size_t)(jt + tid) * 3;
            sPnx[tid] = -p[0]; sPny[tid] = -p[1]; sPnz[tid] = -p[2];
        }
        __syncthreads();

        // ---- GEMM: C = Khi*Vhi^T + Khi*Vlo^T + Klo*Vhi^T (fp32 accum) ----
        float C[2][4][4];
        #pragma unroll
        for (int mt = 0; mt < 2; mt++)
            #pragma unroll
            for (int nt = 0; nt < 4; nt++)
                #pragma unroll
                for (int e = 0; e < 4; e++) C[mt][nt][e] = 0.f;

        #pragma unroll
        for (int kc = 0; kc < 8; kc++) {
            uint32_t ah[2][4], al[2][4], bh[2][4], bl[2][4];
            #pragma unroll
            for (int mt = 0; mt < 2; mt++) {
                uint32_t o = mt * (16 * STRIDE_B) + kc * 32;
                LDSM4(ah[mt], aHiB + o);
                LDSM4(al[mt], aLoB + o);
            }
            #pragma unroll
            for (int ng = 0; ng < 2; ng++) {
                uint32_t o = ng * (16 * STRIDE_B) + kc * 32;
                LDSM4(bh[ng], bHiB + o);
                LDSM4(bl[ng], bLoB + o);
            }
            #pragma unroll
            for (int mt = 0; mt < 2; mt++)
                #pragma unroll
                for (int ng = 0; ng < 2; ng++) {
                    MMA_BF16(C[mt][2 * ng],     ah[mt], bh[ng][0], bh[ng][1]);
                    MMA_BF16(C[mt][2 * ng + 1], ah[mt], bh[ng][2], bh[ng][3]);
                    MMA_BF16(C[mt][2 * ng],     ah[mt], bl[ng][0], bl[ng][1]);
                    MMA_BF16(C[mt][2 * ng + 1], ah[mt], bl[ng][2], bl[ng][3]);
                    MMA_BF16(C[mt][2 * ng],     al[mt], bh[ng][0], bh[ng][1]);
                    MMA_BF16(C[mt][2 * ng + 1], al[mt], bh[ng][2], bh[ng][3]);
                }
        }

        // ---- this thread's 8 column positions (negated) ----
        float njx[8], njy[8], njz[8];
        #pragma unroll
        for (int nt = 0; nt < 4; nt++)
            #pragma unroll
            for (int e = 0; e < 2; e++) {
                int col = 32 * wc + 8 * nt + 2 * qe + e;
                njx[2 * nt + e] = sPnx[col];
                njy[2 * nt + e] = sPny[col];
                njz[2 * nt + e] = sPnz[col];
            }

        // ---- fused epilogue on C fragments ----
        #pragma unroll
        for (int mt = 0; mt < 2; mt++)
            #pragma unroll
            for (int h = 0; h < 2; h++) {
                int ridx = 2 * mt + h;
                float px = pix[ridx], py = piy[ridx], pz = piz[ridx];
                #pragma unroll
                for (int nt = 0; nt < 4; nt++)
                    #pragma unroll
                    for (int e = 0; e < 2; e++) {
                        int cidx = 2 * nt + e;
                        float dx = px + njx[cidx];
                        float dy = py + njy[cidx];
                        float dz = pz + njz[cidx];
                        float d2 = fmaf(dx, dx, fmaf(dy, dy, dz * dz));
                        float inv = rsqrtf(fmaxf(d2, 1e-36f)); // diag -> 0
                        float w = C[mt][nt][2 * h + e] * inv;
                        ax[ridx] = fmaf(w, dx, ax[ridx]);
                        ay[ridx] = fmaf(w, dy, ay[ridx]);
                        az[ridx] = fmaf(w, dz, az[ridx]);
                    }
            }
    }

    // ---- reduce over quad lanes (same rows, different cols) ----
    #pragma unroll
    for (int off = 1; off < 4; off <<= 1)
        #pragma unroll
        for (int r = 0; r < 4; r++) {
            ax[r] += __shfl_xor_sync(0xFFFFFFFFu, ax[r], off);
            ay[r] += __shfl_xor_sync(0xFFFFFFFFu, ay[r], off);
            az[r] += __shfl_xor_sync(0xFFFFFFFFu, az[r], off);
        }

    __syncthreads();
    float* sRed = (float*)(sp + OFF_RED);    // [4 col-groups][128 rows][3]
    if (qe == 0) {
        #pragma unroll
        for (int mt = 0; mt < 2; mt++)
            #pragma unroll
            for (int h = 0; h < 2; h++) {
                int row = 32 * wr + 16 * mt + 8 * h + qid;
                float* d = sRed + (wc * 128 + row) * 3;
                int ridx = 2 * mt + h;
                d[0] = ax[ridx]; d[1] = ay[ridx]; d[2] = az[ridx];
            }
    }
    __syncthreads();

    if (tid < TI) {
        int gi = i0 + tid;
        float sx = 0.f, sy = 0.f, sz = 0.f;
        #pragma unroll
        for (int g = 0; g < 4; g++) {
            const float* d = sRed + (g * 128 + tid) * 3;
            sx += d[0]; sy += d[1]; sz += d[2];
        }
        float s = as * mb[gi];
        float* o = out + ((size_t)b * NATOMS + gi) * 3;
        o[0] = tanhf(sx * inv_msum) * s;
        o[1] = tanhf(sy * inv_msum) * s;
        o[2] = tanhf(sz * inv_msum) * s;
    }
}

extern "C" void kernel_launch(void* const* d_in, const int* in_sizes, int n_in,
                              void* d_out, int out_size) {
    const float* kv   = (const float*)d_in[0];
    const float* pos  = (const float*)d_in[1];
    const float* mask = (const float*)d_in[2];
    const float* asc  = (const float*)d_in[3];
    float* out = (float*)d_out;

    cudaFuncSetAttribute(gen_actions_kernel,
                         cudaFuncAttributeMaxDynamicSharedMemorySize,
                         (int)SMEM_BYTES);

    dim3 grid(NATOMS / TI, BATCH);   // 8 x 16 = 128 blocks, one wave
    gen_actions_kernel<<<grid, THREADS, SMEM_BYTES>>>(kv, pos, mask, asc, out);
}

// round 9
// speedup vs baseline: 4.8126x; 1.1993x over previous
#include <cuda_runtime.h>
#include <cuda_bf16.h>
#include <math.h>
#include <cstdint>

// Shape fixed by dataset: B=16, N=1024, E=128, kv row = 2E+1 = 257
#define BATCH   16
#define NATOMS  1024
#define EDIM    128
#define KVROW   257
#define TI      128
#define TJ      128
#define THREADS 512

// Pre-split bf16 operands, packed 2 per uint32: [b][n][pair] (64 pairs/row)
__device__ uint32_t g_khi[BATCH * NATOMS * 64];
__device__ uint32_t g_klo[BATCH * NATOMS * 64];
__device__ uint32_t g_vhi[BATCH * NATOMS * 64];
__device__ uint32_t g_vlo[BATCH * NATOMS * 64];

// bf16 tile rows padded to 272 B: ldmatrix row offsets mod 128B cycle through
// {0,16,...,112} -> conflict-free without swizzle.
#define STRIDE_B   272
#define TILE_BYTES (128 * STRIDE_B)      // 34816
#define OFF_AHI  0
#define OFF_ALO  34816
#define OFF_BHI0 69632
#define OFF_BLO0 104448
#define OFF_BHI1 139264
#define OFF_BLO1 174080
#define OFF_PQ   208896                  // 2 stages x 128 rows x 3 floats
#define OFF_RED  211968                  // 4 col-groups x 128 rows x 3 floats
#define OFF_MS   218112                  // 16 floats
#define SMEM_BYTES 218240                // < 227KB dynamic max

__device__ __forceinline__ uint32_t smem_u32(const void* p) {
    uint32_t a;
    asm("{ .reg .u64 t; cvta.to.shared.u64 t, %1; cvt.u32.u64 %0, t; }"
        : "=r"(a) : "l"(p));
    return a;
}
__device__ __forceinline__ void cpa16(uint32_t dst, const void* src) {
    asm volatile("cp.async.cg.shared.global [%0], [%1], 16;" :: "r"(dst), "l"(src));
}
__device__ __forceinline__ void cpa4(uint32_t dst, const void* src) {
    asm volatile("cp.async.ca.shared.global [%0], [%1], 4;" :: "r"(dst), "l"(src));
}
#define CP_COMMIT() asm volatile("cp.async.commit_group;" ::: "memory")
#define CP_WAIT(n)  asm volatile("cp.async.wait_group %0;" :: "n"(n) : "memory")

#define LDSM4(r, addr)                                                      \
    asm volatile("ldmatrix.sync.aligned.m8n8.x4.shared.b16 {%0,%1,%2,%3}, [%4];" \
        : "=r"((r)[0]), "=r"((r)[1]), "=r"((r)[2]), "=r"((r)[3]) : "r"(addr))

#define MMA_BF16(c, a, b0_, b1_)                                            \
    asm volatile("mma.sync.aligned.m16n8k16.row.col.f32.bf16.bf16.f32 "     \
        "{%0,%1,%2,%3}, {%4,%5,%6,%7}, {%8,%9}, {%0,%1,%2,%3};"             \
        : "+f"((c)[0]), "+f"((c)[1]), "+f"((c)[2]), "+f"((c)[3])            \
        : "r"((a)[0]), "r"((a)[1]), "r"((a)[2]), "r"((a)[3]),               \
          "r"(b0_), "r"(b1_))

// ---------------- prepass: fp32 -> bf16 hi/lo split, packed pairs ----------
__global__ __launch_bounds__(256)
void split_kv_kernel(const float* __restrict__ kv,
                     const float* __restrict__ mask)
{
    int idx = blockIdx.x * 256 + threadIdx.x;        // [0, B*N*64)
    if (idx >= BATCH * NATOMS * 64) return;
    int p = idx & 63;
    int n = (idx >> 6) & (NATOMS - 1);
    int b = idx >> 16;

    const float* row = kv + ((size_t)b * NATOMS + n) * KVROW;
    float m  = mask[b * NATOMS + n];
    float mk = m * 0.088388347648318447f;            // mask * 1/sqrt(128)

    float k0 = row[2 * p] * mk,        k1 = row[2 * p + 1] * mk;
    float v0 = row[EDIM + 2 * p] * m,  v1 = row[EDIM + 2 * p + 1] * m;

    __nv_bfloat16 kh0 = __float2bfloat16(k0), kh1 = __float2bfloat16(k1);
    __nv_bfloat16 kl0 = __float2bfloat16(k0 - __bfloat162float(kh0));
    __nv_bfloat16 kl1 = __float2bfloat16(k1 - __bfloat162float(kh1));
    __nv_bfloat16 vh0 = __float2bfloat16(v0), vh1 = __float2bfloat16(v1);
    __nv_bfloat16 vl0 = __float2bfloat16(v0 - __bfloat162float(vh0));
    __nv_bfloat16 vl1 = __float2bfloat16(v1 - __bfloat162float(vh1));

    g_khi[idx] = (uint32_t)__bfloat16_as_ushort(kh0) | ((uint32_t)__bfloat16_as_ushort(kh1) << 16);
    g_klo[idx] = (uint32_t)__bfloat16_as_ushort(kl0) | ((uint32_t)__bfloat16_as_ushort(kl1) << 16);
    g_vhi[idx] = (uint32_t)__bfloat16_as_ushort(vh0) | ((uint32_t)__bfloat16_as_ushort(vh1) << 16);
    g_vlo[idx] = (uint32_t)__bfloat16_as_ushort(vl0) | ((uint32_t)__bfloat16_as_ushort(vl1) << 16);
}

// ---------------- main kernel ----------------------------------------------
__global__ __launch_bounds__(THREADS, 1)
void gen_actions_kernel(const float* __restrict__ pos,
                        const float* __restrict__ mask,
                        const float* __restrict__ ascale,
                        float* __restrict__ out)
{
    extern __shared__ char sp[];
    const uint32_t sb = smem_u32(sp);

    const int tid  = threadIdx.x;
    const int wid  = tid >> 5;
    const int lane = tid & 31;
    const int wr   = wid & 3;       // warp row: S rows [32wr, 32wr+32)
    const int wc   = wid >> 2;      // warp col: S cols [32wc, 32wc+32)
    const int qid  = lane >> 2;
    const int qe   = lane & 3;

    const int b  = blockIdx.y;
    const int i0 = blockIdx.x * TI;

    const float* mb = mask + (size_t)b * NATOMS;
    const float* pb = pos  + (size_t)b * NATOMS * 3;

    // ---- prologue: async-load A tiles (khi/klo for this i-tile) + B tile 0 ----
    {
        const uint32_t* ah = g_khi + ((size_t)b * NATOMS + i0) * 64;
        const uint32_t* al = g_klo + ((size_t)b * NATOMS + i0) * 64;
        #pragma unroll
        for (int it = 0; it < 4; it++) {
            int idx = tid + it * THREADS;          // [0,2048): r=idx>>4, c=idx&15
            int r = idx >> 4, c = idx & 15;
            cpa16(sb + OFF_AHI + r * STRIDE_B + c * 16, ah + r * 64 + c * 4);
            cpa16(sb + OFF_ALO + r * STRIDE_B + c * 16, al + r * 64 + c * 4);
        }
        const uint32_t* bh = g_vhi + (size_t)b * NATOMS * 64;   // jt = 0
        const uint32_t* bl = g_vlo + (size_t)b * NATOMS * 64;
        #pragma unroll
        for (int it = 0; it < 4; it++) {
            int idx = tid + it * THREADS;
            int r = idx >> 4, c = idx & 15;
            cpa16(sb + OFF_BHI0 + r * STRIDE_B + c * 16, bh + r * 64 + c * 4);
            cpa16(sb + OFF_BLO0 + r * STRIDE_B + c * 16, bl + r * 64 + c * 4);
        }
        if (tid < 384) cpa4(sb + OFF_PQ + tid * 4, pb + tid);
        CP_COMMIT();
    }

    // ---- mask sum (overlaps with async loads) ----
    {
        float* sMS = (float*)(sp + OFF_MS);
        float ms = 0.f;
        for (int n = tid; n < NATOMS; n += THREADS) ms += mb[n];
        #pragma unroll
        for (int off = 16; off > 0; off >>= 1)
            ms += __shfl_xor_sync(0xFFFFFFFFu, ms, off);
        if (lane == 0) sMS[wid] = ms;
    }
    __syncthreads();
    float msum = 0.f;
    {
        float* sMS = (float*)(sp + OFF_MS);
        #pragma unroll
        for (int q = 0; q < 16; q++) msum += sMS[q];
    }
    const float inv_msum = 1.0f / msum;
    const float as = ascale[0];

    // ---- this thread's 4 fixed rows: 32wr + 16mt + 8h + qid ----
    float pix[4], piy[4], piz[4];
    #pragma unroll
    for (int mt = 0; mt < 2; mt++)
        #pragma unroll
        for (int h = 0; h < 2; h++) {
            int gi = i0 + 32 * wr + 16 * mt + 8 * h + qid;
            const float* p = pb + (size_t)gi * 3;
            pix[2 * mt + h] = p[0]; piy[2 * mt + h] = p[1]; piz[2 * mt + h] = p[2];
        }

    // ---- ldmatrix lane base addresses (conflict-free) ----
    const uint32_t aRow = 32 * wr + (lane & 15);
    const uint32_t aKof = (lane & 16) ? 16u : 0u;
    const uint32_t aHiB = sb + OFF_AHI + aRow * STRIDE_B + aKof;
    const uint32_t aLoB = sb + OFF_ALO + aRow * STRIDE_B + aKof;
    const uint32_t bRow = 32 * wc + (lane & 7) + ((lane & 16) ? 8 : 0);
    const uint32_t bKof = (lane & 8) ? 16u : 0u;
    const uint32_t bLaneOff = bRow * STRIDE_B + bKof;

    float ax[4], ay[4], az[4];
    #pragma unroll
    for (int r = 0; r < 4; r++) { ax[r] = 0.f; ay[r] = 0.f; az[r] = 0.f; }

    for (int t = 0; t < NATOMS / TJ; t++) {
        // issue next tile into the other stage, then wait for current stage
        if (t < 7) {
            const int jn = (t + 1) * TJ;
            const uint32_t bhiN = ((t + 1) & 1) ? OFF_BHI1 : OFF_BHI0;
            const uint32_t bloN = ((t + 1) & 1) ? OFF_BLO1 : OFF_BLO0;
            const uint32_t* bh = g_vhi + ((size_t)b * NATOMS + jn) * 64;
            const uint32_t* bl = g_vlo + ((size_t)b * NATOMS + jn) * 64;
            #pragma unroll
            for (int it = 0; it < 4; it++) {
                int idx = tid + it * THREADS;
                int r = idx >> 4, c = idx & 15;
                cpa16(sb + bhiN + r * STRIDE_B + c * 16, bh + r * 64 + c * 4);
                cpa16(sb + bloN + r * STRIDE_B + c * 16, bl + r * 64 + c * 4);
            }
            if (tid < 384)
                cpa4(sb + OFF_PQ + ((t + 1) & 1) * 1536 + tid * 4, pb + jn * 3 + tid);
            CP_COMMIT();
            CP_WAIT(1);          // current stage's group complete
        } else {
            CP_WAIT(0);
        }
        __syncthreads();         // cp.async completion visible block-wide

        const uint32_t bhiC = (t & 1) ? OFF_BHI1 : OFF_BHI0;
        const uint32_t bloC = (t & 1) ? OFF_BLO1 : OFF_BLO0;
        const uint32_t bHiB = sb + bhiC + bLaneOff;
        const uint32_t bLoB = sb + bloC + bLaneOff;
        const float* sPq = (const float*)(sp + OFF_PQ + (t & 1) * 1536);

        // ---- GEMM: C = Khi*Vhi^T + Khi*Vlo^T + Klo*Vhi^T (fp32 accum) ----
        float C[2][4][4];
        #pragma unroll
        for (int mt = 0; mt < 2; mt++)
            #pragma unroll
            for (int nt = 0; nt < 4; nt++)
                #pragma unroll
                for (int e = 0; e < 4; e++) C[mt][nt][e] = 0.f;

        #pragma unroll
        for (int kc = 0; kc < 8; kc++) {
            uint32_t ah[2][4], al[2][4], bh[2][4], bl[2][4];
            #pragma unroll
            for (int mt = 0; mt < 2; mt++) {
                uint32_t o = mt * (16 * STRIDE_B) + kc * 32;
                LDSM4(ah[mt], aHiB + o);
                LDSM4(al[mt], aLoB + o);
            }
            #pragma unroll
            for (int ng = 0; ng < 2; ng++) {
                uint32_t o = ng * (16 * STRIDE_B) + kc * 32;
                LDSM4(bh[ng], bHiB + o);
                LDSM4(bl[ng], bLoB + o);
            }
            #pragma unroll
            for (int mt = 0; mt < 2; mt++)
                #pragma unroll
                for (int ng = 0; ng < 2; ng++) {
                    MMA_BF16(C[mt][2 * ng],     ah[mt], bh[ng][0], bh[ng][1]);
                    MMA_BF16(C[mt][2 * ng + 1], ah[mt], bh[ng][2], bh[ng][3]);
                    MMA_BF16(C[mt][2 * ng],     ah[mt], bl[ng][0], bl[ng][1]);
                    MMA_BF16(C[mt][2 * ng + 1], ah[mt], bl[ng][2], bl[ng][3]);
                    MMA_BF16(C[mt][2 * ng],     al[mt], bh[ng][0], bh[ng][1]);
                    MMA_BF16(C[mt][2 * ng + 1], al[mt], bh[ng][2], bh[ng][3]);
                }
        }

        // ---- this thread's 8 column positions ----
        float qx[8], qy[8], qz[8];
        #pragma unroll
        for (int nt = 0; nt < 4; nt++)
            #pragma unroll
            for (int e = 0; e < 2; e++) {
                int col = 32 * wc + 8 * nt + 2 * qe + e;
                qx[2 * nt + e] = sPq[col * 3 + 0];
                qy[2 * nt + e] = sPq[col * 3 + 1];
                qz[2 * nt + e] = sPq[col * 3 + 2];
            }

        // ---- fused epilogue on C fragments ----
        #pragma unroll
        for (int mt = 0; mt < 2; mt++)
            #pragma unroll
            for (int h = 0; h < 2; h++) {
                int ridx = 2 * mt + h;
                float px = pix[ridx], py = piy[ridx], pz = piz[ridx];
                #pragma unroll
                for (int nt = 0; nt < 4; nt++)
                    #pragma unroll
                    for (int e = 0; e < 2; e++) {
                        int cidx = 2 * nt + e;
                        float dx = px - qx[cidx];
                        float dy = py - qy[cidx];
                        float dz = pz - qz[cidx];
                        float d2 = fmaf(dx, dx, fmaf(dy, dy, dz * dz));
                        float inv = rsqrtf(fmaxf(d2, 1e-36f)); // diag -> 0
                        float w = C[mt][nt][2 * h + e] * inv;
                        ax[ridx] = fmaf(w, dx, ax[ridx]);
                        ay[ridx] = fmaf(w, dy, ay[ridx]);
                        az[ridx] = fmaf(w, dz, az[ridx]);
                    }
            }
        __syncthreads();   // stage fully consumed before it is refilled
    }

    // ---- reduce over quad lanes (same rows, different cols) ----
    #pragma unroll
    for (int off = 1; off < 4; off <<= 1)
        #pragma unroll
        for (int r = 0; r < 4; r++) {
            ax[r] += __shfl_xor_sync(0xFFFFFFFFu, ax[r], off);
            ay[r] += __shfl_xor_sync(0xFFFFFFFFu, ay[r], off);
            az[r] += __shfl_xor_sync(0xFFFFFFFFu, az[r], off);
        }

    float* sRed = (float*)(sp + OFF_RED);    // [4 col-groups][128 rows][3]
    if (qe == 0) {
        #pragma unroll
        for (int mt = 0; mt < 2; mt++)
            #pragma unroll
            for (int h = 0; h < 2; h++) {
                int row = 32 * wr + 16 * mt + 8 * h + qid;
                float* d = sRed + (wc * 128 + row) * 3;
                int ridx = 2 * mt + h;
                d[0] = ax[ridx]; d[1] = ay[ridx]; d[2] = az[ridx];
            }
    }
    __syncthreads();

    if (tid < TI) {
        int gi = i0 + tid;
        float sx = 0.f, sy = 0.f, sz = 0.f;
        #pragma unroll
        for (int g = 0; g < 4; g++) {
            const float* d = sRed + (g * 128 + tid) * 3;
            sx += d[0]; sy += d[1]; sz += d[2];
        }
        float s = as * mb[gi];
        float* o = out + ((size_t)b * NATOMS + gi) * 3;
        o[0] = tanhf(sx * inv_msum) * s;
        o[1] = tanhf(sy * inv_msum) * s;
        o[2] = tanhf(sz * inv_msum) * s;
    }
}

extern "C" void kernel_launch(void* const* d_in, const int* in_sizes, int n_in,
                              void* d_out, int out_size) {
    const float* kv   = (const float*)d_in[0];
    const float* pos  = (const float*)d_in[1];
    const float* mask = (const float*)d_in[2];
    const float* asc  = (const float*)d_in[3];
    float* out = (float*)d_out;

    cudaFuncSetAttribute(gen_actions_kernel,
                         cudaFuncAttributeMaxDynamicSharedMemorySize,
                         (int)SMEM_BYTES);

    split_kv_kernel<<<(BATCH * NATOMS * 64 + 255) / 256, 256>>>(kv, mask);

    dim3 grid(NATOMS / TI, BATCH);   // 8 x 16 = 128 blocks, one wave
    gen_actions_kernel<<<grid, THREADS, SMEM_BYTES>>>(pos, mask, asc, out);
}

// round 10
// speedup vs baseline: 4.8791x; 1.0138x over previous
#include <cuda_runtime.h>
#include <cuda_bf16.h>
#include <math.h>
#include <cstdint>

// Shape fixed by dataset: B=16, N=1024, E=128, kv row = 2E+1 = 257
#define BATCH   16
#define NATOMS  1024
#define EDIM    128
#define KVROW   257
#define TI      128
#define TJ      128
#define THREADS 512

// Pre-split bf16 operands, packed 2 per uint32: [b][n][pair] (64 pairs/row)
__device__ uint32_t g_khi[BATCH * NATOMS * 64];
__device__ uint32_t g_klo[BATCH * NATOMS * 64];
__device__ uint32_t g_vhi[BATCH * NATOMS * 64];
__device__ uint32_t g_vlo[BATCH * NATOMS * 64];

// bf16 tile rows padded to 272 B: ldmatrix row offsets mod 128B cycle through
// {0,16,...,112} -> conflict-free without swizzle.
#define STRIDE_B   272
#define TILE_BYTES (128 * STRIDE_B)      // 34816
#define OFF_AHI  0
#define OFF_ALO  34816
#define OFF_BHI0 69632
#define OFF_BLO0 104448
#define OFF_BHI1 139264
#define OFF_BLO1 174080
#define OFF_PQ   208896                  // 4 stages x 384 floats = 6144 B
#define OFF_RED  215040                  // 4 col-groups x 128 rows x 3 floats
#define OFF_MS   221184                  // 16 floats
#define SMEM_BYTES 221248                // < 227KB dynamic max

__device__ __forceinline__ uint32_t smem_u32(const void* p) {
    uint32_t a;
    asm("{ .reg .u64 t; cvta.to.shared.u64 t, %1; cvt.u32.u64 %0, t; }"
        : "=r"(a) : "l"(p));
    return a;
}
__device__ __forceinline__ void cpa16(uint32_t dst, const void* src) {
    asm volatile("cp.async.cg.shared.global [%0], [%1], 16;" :: "r"(dst), "l"(src));
}
__device__ __forceinline__ void cpa4(uint32_t dst, const void* src) {
    asm volatile("cp.async.ca.shared.global [%0], [%1], 4;" :: "r"(dst), "l"(src));
}
#define CP_COMMIT() asm volatile("cp.async.commit_group;" ::: "memory")
#define CP_WAIT0()  asm volatile("cp.async.wait_group 0;" ::: "memory")

#define LDSM4(r, addr)                                                      \
    asm volatile("ldmatrix.sync.aligned.m8n8.x4.shared.b16 {%0,%1,%2,%3}, [%4];" \
        : "=r"((r)[0]), "=r"((r)[1]), "=r"((r)[2]), "=r"((r)[3]) : "r"(addr))

#define MMA_BF16(c, a, b0_, b1_)                                            \
    asm volatile("mma.sync.aligned.m16n8k16.row.col.f32.bf16.bf16.f32 "     \
        "{%0,%1,%2,%3}, {%4,%5,%6,%7}, {%8,%9}, {%0,%1,%2,%3};"             \
        : "+f"((c)[0]), "+f"((c)[1]), "+f"((c)[2]), "+f"((c)[3])            \
        : "r"((a)[0]), "r"((a)[1]), "r"((a)[2]), "r"((a)[3]),               \
          "r"(b0_), "r"(b1_))

// ---------------- prepass: fp32 -> bf16 hi/lo split, packed pairs ----------
__global__ __launch_bounds__(256)
void split_kv_kernel(const float* __restrict__ kv,
                     const float* __restrict__ mask)
{
    int idx = blockIdx.x * 256 + threadIdx.x;        // [0, B*N*64)
    if (idx >= BATCH * NATOMS * 64) return;
    int p = idx & 63;
    int n = (idx >> 6) & (NATOMS - 1);
    int b = idx >> 16;

    const float* row = kv + ((size_t)b * NATOMS + n) * KVROW;
    float m  = mask[b * NATOMS + n];
    float mk = m * 0.088388347648318447f;            // mask * 1/sqrt(128)

    float k0 = row[2 * p] * mk,        k1 = row[2 * p + 1] * mk;
    float v0 = row[EDIM + 2 * p] * m,  v1 = row[EDIM + 2 * p + 1] * m;

    __nv_bfloat16 kh0 = __float2bfloat16(k0), kh1 = __float2bfloat16(k1);
    __nv_bfloat16 kl0 = __float2bfloat16(k0 - __bfloat162float(kh0));
    __nv_bfloat16 kl1 = __float2bfloat16(k1 - __bfloat162float(kh1));
    __nv_bfloat16 vh0 = __float2bfloat16(v0), vh1 = __float2bfloat16(v1);
    __nv_bfloat16 vl0 = __float2bfloat16(v0 - __bfloat162float(vh0));
    __nv_bfloat16 vl1 = __float2bfloat16(v1 - __bfloat162float(vh1));

    g_khi[idx] = (uint32_t)__bfloat16_as_ushort(kh0) | ((uint32_t)__bfloat16_as_ushort(kh1) << 16);
    g_klo[idx] = (uint32_t)__bfloat16_as_ushort(kl0) | ((uint32_t)__bfloat16_as_ushort(kl1) << 16);
    g_vhi[idx] = (uint32_t)__bfloat16_as_ushort(vh0) | ((uint32_t)__bfloat16_as_ushort(vh1) << 16);
    g_vlo[idx] = (uint32_t)__bfloat16_as_ushort(vl0) | ((uint32_t)__bfloat16_as_ushort(vl1) << 16);
}

// ---------------- GEMM: 3-pass bf16 split, C += K.V^T ----------------------
__device__ __forceinline__ void gemm_tile(float (&C)[2][4][4],
    uint32_t aHiB, uint32_t aLoB, uint32_t bHiB, uint32_t bLoB)
{
    #pragma unroll
    for (int mt = 0; mt < 2; mt++)
        #pragma unroll
        for (int nt = 0; nt < 4; nt++)
            #pragma unroll
            for (int e = 0; e < 4; e++) C[mt][nt][e] = 0.f;

    #pragma unroll
    for (int kc = 0; kc < 8; kc++) {
        uint32_t ah[2][4], al[2][4], bh[2][4], bl[2][4];
        #pragma unroll
        for (int mt = 0; mt < 2; mt++) {
            uint32_t o = mt * (16 * STRIDE_B) + kc * 32;
            LDSM4(ah[mt], aHiB + o);
            LDSM4(al[mt], aLoB + o);
        }
        #pragma unroll
        for (int ng = 0; ng < 2; ng++) {
            uint32_t o = ng * (16 * STRIDE_B) + kc * 32;
            LDSM4(bh[ng], bHiB + o);
            LDSM4(bl[ng], bLoB + o);
        }
        #pragma unroll
        for (int mt = 0; mt < 2; mt++)
            #pragma unroll
            for (int ng = 0; ng < 2; ng++) {
                MMA_BF16(C[mt][2 * ng],     ah[mt], bh[ng][0], bh[ng][1]);
                MMA_BF16(C[mt][2 * ng + 1], ah[mt], bh[ng][2], bh[ng][3]);
                MMA_BF16(C[mt][2 * ng],     ah[mt], bl[ng][0], bl[ng][1]);
                MMA_BF16(C[mt][2 * ng + 1], ah[mt], bl[ng][2], bl[ng][3]);
                MMA_BF16(C[mt][2 * ng],     al[mt], bh[ng][0], bh[ng][1]);
                MMA_BF16(C[mt][2 * ng + 1], al[mt], bh[ng][2], bh[ng][3]);
            }
    }
}

// ---------------- epilogue on C fragments, q read from smem stage ----------
__device__ __forceinline__ void epi_tile(const float (&C)[2][4][4],
    const float* sPq, int wc, int qe,
    const float (&pix)[4], const float (&piy)[4], const float (&piz)[4],
    float (&ax)[4], float (&ay)[4], float (&az)[4])
{
    float qx[8], qy[8], qz[8];
    #pragma unroll
    for (int nt = 0; nt < 4; nt++)
        #pragma unroll
        for (int e = 0; e < 2; e++) {
            int col = 32 * wc + 8 * nt + 2 * qe + e;
            qx[2 * nt + e] = sPq[col * 3 + 0];
            qy[2 * nt + e] = sPq[col * 3 + 1];
            qz[2 * nt + e] = sPq[col * 3 + 2];
        }
    #pragma unroll
    for (int mt = 0; mt < 2; mt++)
        #pragma unroll
        for (int h = 0; h < 2; h++) {
            int ridx = 2 * mt + h;
            float px = pix[ridx], py = piy[ridx], pz = piz[ridx];
            #pragma unroll
            for (int nt = 0; nt < 4; nt++)
                #pragma unroll
                for (int e = 0; e < 2; e++) {
                    int cidx = 2 * nt + e;
                    float dx = px - qx[cidx];
                    float dy = py - qy[cidx];
                    float dz = pz - qz[cidx];
                    float d2 = fmaf(dx, dx, fmaf(dy, dy, dz * dz));
                    float inv = rsqrtf(fmaxf(d2, 1e-36f)); // diag -> 0
                    float w = C[mt][nt][2 * h + e] * inv;
                    ax[ridx] = fmaf(w, dx, ax[ridx]);
                    ay[ridx] = fmaf(w, dy, ay[ridx]);
                    az[ridx] = fmaf(w, dz, az[ridx]);
                }
        }
}

// ---------------- refill: async-load tile jn into B buffers + pos stage ----
__device__ __forceinline__ void issue_refill(uint32_t sb, int tid, int b, int jn,
                                             uint32_t bhiOff, uint32_t bloOff,
                                             const float* pb)
{
    const uint32_t* bh = g_vhi + ((size_t)b * NATOMS + jn) * 64;
    const uint32_t* bl = g_vlo + ((size_t)b * NATOMS + jn) * 64;
    #pragma unroll
    for (int it = 0; it < 4; it++) {
        int idx = tid + it * THREADS;
        int r = idx >> 4, c = idx & 15;
        cpa16(sb + bhiOff + r * STRIDE_B + c * 16, bh + r * 64 + c * 4);
        cpa16(sb + bloOff + r * STRIDE_B + c * 16, bl + r * 64 + c * 4);
    }
    if (tid < 384) {
        int stage = (jn / TJ) & 3;
        cpa4(sb + OFF_PQ + stage * 1536 + tid * 4, pb + jn * 3 + tid);
    }
    CP_COMMIT();
}

// ---------------- main kernel ----------------------------------------------
__global__ __launch_bounds__(THREADS, 1)
void gen_actions_kernel(const float* __restrict__ pos,
                        const float* __restrict__ mask,
                        const float* __restrict__ ascale,
                        float* __restrict__ out)
{
    extern __shared__ char sp[];
    const uint32_t sb = smem_u32(sp);

    const int tid  = threadIdx.x;
    const int wid  = tid >> 5;
    const int lane = tid & 31;
    const int wr   = wid & 3;       // warp row: S rows [32wr, 32wr+32)
    const int wc   = wid >> 2;      // warp col: S cols [32wc, 32wc+32)
    const int qid  = lane >> 2;
    const int qe   = lane & 3;

    const int b  = blockIdx.y;
    const int i0 = blockIdx.x * TI;

    const float* mb = mask + (size_t)b * NATOMS;
    const float* pb = pos  + (size_t)b * NATOMS * 3;

    // ---- prologue: A tiles + B tile 0 + pos stage 0, ONE group ----
    {
        const uint32_t* ah = g_khi + ((size_t)b * NATOMS + i0) * 64;
        const uint32_t* al = g_klo + ((size_t)b * NATOMS + i0) * 64;
        const uint32_t* bh = g_vhi + (size_t)b * NATOMS * 64;   // jt = 0
        const uint32_t* bl = g_vlo + (size_t)b * NATOMS * 64;
        #pragma unroll
        for (int it = 0; it < 4; it++) {
            int idx = tid + it * THREADS;
            int r = idx >> 4, c = idx & 15;
            cpa16(sb + OFF_AHI  + r * STRIDE_B + c * 16, ah + r * 64 + c * 4);
            cpa16(sb + OFF_ALO  + r * STRIDE_B + c * 16, al + r * 64 + c * 4);
            cpa16(sb + OFF_BHI0 + r * STRIDE_B + c * 16, bh + r * 64 + c * 4);
            cpa16(sb + OFF_BLO0 + r * STRIDE_B + c * 16, bl + r * 64 + c * 4);
        }
        if (tid < 384) cpa4(sb + OFF_PQ + tid * 4, pb + tid);
        CP_COMMIT();
    }

    // ---- mask sum (overlaps the async loads) ----
    {
        float* sMS = (float*)(sp + OFF_MS);
        float ms = 0.f;
        for (int n = tid; n < NATOMS; n += THREADS) ms += mb[n];
        #pragma unroll
        for (int off = 16; off > 0; off >>= 1)
            ms += __shfl_xor_sync(0xFFFFFFFFu, ms, off);
        if (lane == 0) sMS[wid] = ms;
        __syncthreads();
        ms = 0.f;
        #pragma unroll
        for (int q = 0; q < 16; q++) ms += sMS[q];
        sMS[16 + wid] = ms;   // scratch (unused), keep msum in reg below
    }
    float msum = 0.f;
    {
        float* sMS = (float*)(sp + OFF_MS);
        #pragma unroll
        for (int q = 0; q < 16; q++) msum += sMS[q];
    }
    const float inv_msum = 1.0f / msum;
    const float as = ascale[0];

    // ---- this thread's 4 fixed rows: 32wr + 16mt + 8h + qid ----
    float pix[4], piy[4], piz[4];
    #pragma unroll
    for (int mt = 0; mt < 2; mt++)
        #pragma unroll
        for (int h = 0; h < 2; h++) {
            int gi = i0 + 32 * wr + 16 * mt + 8 * h + qid;
            const float* p = pb + (size_t)gi * 3;
            pix[2 * mt + h] = p[0]; piy[2 * mt + h] = p[1]; piz[2 * mt + h] = p[2];
        }

    // ---- ldmatrix lane base addresses (conflict-free) ----
    const uint32_t aRow = 32 * wr + (lane & 15);
    const uint32_t aKof = (lane & 16) ? 16u : 0u;
    const uint32_t aHiB = sb + OFF_AHI + aRow * STRIDE_B + aKof;
    const uint32_t aLoB = sb + OFF_ALO + aRow * STRIDE_B + aKof;
    const uint32_t bRow = 32 * wc + (lane & 7) + ((lane & 16) ? 8 : 0);
    const uint32_t bKof = (lane & 8) ? 16u : 0u;
    const uint32_t bLaneOff = bRow * STRIDE_B + bKof;

    float ax[4], ay[4], az[4];
    #pragma unroll
    for (int r = 0; r < 4; r++) { ax[r] = 0.f; ay[r] = 0.f; az[r] = 0.f; }

    float C0[2][4][4], C1[2][4][4];
    const float* sPqBase = (const float*)(sp + OFF_PQ);

    // Pipeline: GEMM(t) -> C[t&1]; epilogue(t-1) on C[(t-1)&1] overlaps the
    // tensor pipe draining tile t's MMAs. One wait+barrier per tile; refill
    // of buf (t+1)&1 is safe right after the barrier (consumed at t-1).
    for (int tp = 0; tp < 8; tp += 2) {
        // ---- even tile t = tp (buf0) ----
        CP_WAIT0();
        __syncthreads();
        if (tp < 7)
            issue_refill(sb, tid, b, (tp + 1) * TJ, OFF_BHI1, OFF_BLO1, pb);
        gemm_tile(C0, aHiB, aLoB, sb + OFF_BHI0 + bLaneOff, sb + OFF_BLO0 + bLaneOff);
        if (tp > 0)
            epi_tile(C1, sPqBase + ((tp - 1) & 3) * 384, wc, qe,
                     pix, piy, piz, ax, ay, az);

        // ---- odd tile t = tp+1 (buf1) ----
        CP_WAIT0();
        __syncthreads();
        if (tp + 1 < 7)
            issue_refill(sb, tid, b, (tp + 2) * TJ, OFF_BHI0, OFF_BLO0, pb);
        gemm_tile(C1, aHiB, aLoB, sb + OFF_BHI1 + bLaneOff, sb + OFF_BLO1 + bLaneOff);
        epi_tile(C0, sPqBase + (tp & 3) * 384, wc, qe,
                 pix, piy, piz, ax, ay, az);
    }
    // tail: tile 7 epilogue
    epi_tile(C1, sPqBase + 3 * 384, wc, qe, pix, piy, piz, ax, ay, az);

    // ---- reduce over quad lanes (same rows, different cols) ----
    #pragma unroll
    for (int off = 1; off < 4; off <<= 1)
        #pragma unroll
        for (int r = 0; r < 4; r++) {
            ax[r] += __shfl_xor_sync(0xFFFFFFFFu, ax[r], off);
            ay[r] += __shfl_xor_sync(0xFFFFFFFFu, ay[r], off);
            az[r] += __shfl_xor_sync(0xFFFFFFFFu, az[r], off);
        }

    __syncthreads();
    float* sRed = (float*)(sp + OFF_RED);    // [4 col-groups][128 rows][3]
    if (qe == 0) {
        #pragma unroll
        for (int mt = 0; mt < 2; mt++)
            #pragma unroll
            for (int h = 0; h < 2; h++) {
                int row = 32 * wr + 16 * mt + 8 * h + qid;
                float* d = sRed + (wc * 128 + row) * 3;
                int ridx = 2 * mt + h;
                d[0] = ax[ridx]; d[1] = ay[ridx]; d[2] = az[ridx];
            }
    }
    __syncthreads();

    if (tid < TI) {
        int gi = i0 + tid;
        float sx = 0.f, sy = 0.f, sz = 0.f;
        #pragma unroll
        for (int g = 0; g < 4; g++) {
            const float* d = sRed + (g * 128 + tid) * 3;
            sx += d[0]; sy += d[1]; sz += d[2];
        }
        float s = as * mb[gi];
        float* o = out + ((size_t)b * NATOMS + gi) * 3;
        o[0] = tanhf(sx * inv_msum) * s;
        o[1] = tanhf(sy * inv_msum) * s;
        o[2] = tanhf(sz * inv_msum) * s;
    }
}

extern "C" void kernel_launch(void* const* d_in, const int* in_sizes, int n_in,
                              void* d_out, int out_size) {
    const float* kv   = (const float*)d_in[0];
    const float* pos  = (const float*)d_in[1];
    const float* mask = (const float*)d_in[2];
    const float* asc  = (const float*)d_in[3];
    float* out = (float*)d_out;

    cudaFuncSetAttribute(gen_actions_kernel,
                         cudaFuncAttributeMaxDynamicSharedMemorySize,
                         (int)SMEM_BYTES);

    split_kv_kernel<<<(BATCH * NATOMS * 64 + 255) / 256, 256>>>(kv, mask);

    dim3 grid(NATOMS / TI, BATCH);   // 8 x 16 = 128 blocks, one wave
    gen_actions_kernel<<<grid, THREADS, SMEM_BYTES>>>(pos, mask, asc, out);
}

// round 11
// speedup vs baseline: 4.9017x; 1.0046x over previous
#include <cuda_runtime.h>
#include <cuda_bf16.h>
#include <math.h>
#include <cstdint>

// Shape fixed by dataset: B=16, N=1024, E=128, kv row = 2E+1 = 257
#define BATCH   16
#define NATOMS  1024
#define EDIM    128
#define KVROW   257
#define TI      128
#define TJ      128
#define THREADS 512

// Pre-split bf16 operands, packed 2 per uint32: [b][n][pair] (64 pairs/row)
__device__ uint32_t g_khi[BATCH * NATOMS * 64];
__device__ uint32_t g_klo[BATCH * NATOMS * 64];
__device__ uint32_t g_vhi[BATCH * NATOMS * 64];
__device__ uint32_t g_vlo[BATCH * NATOMS * 64];

// bf16 tile rows padded to 272 B: ldmatrix row offsets mod 128B cycle through
// {0,16,...,112} -> conflict-free without swizzle.
#define STRIDE_B   272
#define TILE_BYTES (128 * STRIDE_B)      // 34816
#define OFF_AHI  0
#define OFF_ALO  34816
#define OFF_BHI0 69632
#define OFF_BLO0 104448
#define OFF_BHI1 139264
#define OFF_BLO1 174080
#define OFF_PQ   208896                  // 4 stages x 384 floats = 6144 B
#define OFF_RED  215040                  // 4 col-groups x 128 rows x 3 floats
#define OFF_MS   221184                  // 16 floats
#define SMEM_BYTES 221248                // < 227KB dynamic max

__device__ __forceinline__ uint32_t smem_u32(const void* p) {
    uint32_t a;
    asm("{ .reg .u64 t; cvta.to.shared.u64 t, %1; cvt.u32.u64 %0, t; }"
        : "=r"(a) : "l"(p));
    return a;
}
__device__ __forceinline__ void cpa16(uint32_t dst, const void* src) {
    asm volatile("cp.async.cg.shared.global [%0], [%1], 16;" :: "r"(dst), "l"(src));
}
__device__ __forceinline__ void cpa4(uint32_t dst, const void* src) {
    asm volatile("cp.async.ca.shared.global [%0], [%1], 4;" :: "r"(dst), "l"(src));
}
#define CP_COMMIT() asm volatile("cp.async.commit_group;" ::: "memory")
#define CP_WAIT0()  asm volatile("cp.async.wait_group 0;" ::: "memory")

#define LDSM4(r, addr)                                                      \
    asm volatile("ldmatrix.sync.aligned.m8n8.x4.shared.b16 {%0,%1,%2,%3}, [%4];" \
        : "=r"((r)[0]), "=r"((r)[1]), "=r"((r)[2]), "=r"((r)[3]) : "r"(addr))

#define MMA_BF16(c, a, b0_, b1_)                                            \
    asm volatile("mma.sync.aligned.m16n8k16.row.col.f32.bf16.bf16.f32 "     \
        "{%0,%1,%2,%3}, {%4,%5,%6,%7}, {%8,%9}, {%0,%1,%2,%3};"             \
        : "+f"((c)[0]), "+f"((c)[1]), "+f"((c)[2]), "+f"((c)[3])            \
        : "r"((a)[0]), "r"((a)[1]), "r"((a)[2]), "r"((a)[3]),               \
          "r"(b0_), "r"(b1_))

// ---------------- prepass: fp32 -> bf16 hi/lo split, packed pairs ----------
__global__ __launch_bounds__(256)
void split_kv_kernel(const float* __restrict__ kv,
                     const float* __restrict__ mask)
{
    int idx = blockIdx.x * 256 + threadIdx.x;        // [0, B*N*64)
    if (idx >= BATCH * NATOMS * 64) return;
    int p = idx & 63;
    int n = (idx >> 6) & (NATOMS - 1);
    int b = idx >> 16;

    const float* row = kv + ((size_t)b * NATOMS + n) * KVROW;
    float m  = mask[b * NATOMS + n];
    float mk = m * 0.088388347648318447f;            // mask * 1/sqrt(128)

    float k0 = row[2 * p] * mk,        k1 = row[2 * p + 1] * mk;
    float v0 = row[EDIM + 2 * p] * m,  v1 = row[EDIM + 2 * p + 1] * m;

    __nv_bfloat16 kh0 = __float2bfloat16(k0), kh1 = __float2bfloat16(k1);
    __nv_bfloat16 kl0 = __float2bfloat16(k0 - __bfloat162float(kh0));
    __nv_bfloat16 kl1 = __float2bfloat16(k1 - __bfloat162float(kh1));
    __nv_bfloat16 vh0 = __float2bfloat16(v0), vh1 = __float2bfloat16(v1);
    __nv_bfloat16 vl0 = __float2bfloat16(v0 - __bfloat162float(vh0));
    __nv_bfloat16 vl1 = __float2bfloat16(v1 - __bfloat162float(vh1));

    g_khi[idx] = (uint32_t)__bfloat16_as_ushort(kh0) | ((uint32_t)__bfloat16_as_ushort(kh1) << 16);
    g_klo[idx] = (uint32_t)__bfloat16_as_ushort(kl0) | ((uint32_t)__bfloat16_as_ushort(kl1) << 16);
    g_vhi[idx] = (uint32_t)__bfloat16_as_ushort(vh0) | ((uint32_t)__bfloat16_as_ushort(vh1) << 16);
    g_vlo[idx] = (uint32_t)__bfloat16_as_ushort(vl0) | ((uint32_t)__bfloat16_as_ushort(vl1) << 16);
}

// GEMM tile, 3-pass split. MMAs grouped so each pass touches all 8 distinct
// C fragments before any fragment is revisited (RAW reuse distance 2 -> 8).
__device__ __forceinline__ void gemm_tile(float (&C)[2][4][4],
    uint32_t aHiB, uint32_t aLoB, uint32_t bHiB, uint32_t bLoB)
{
    #pragma unroll
    for (int mt = 0; mt < 2; mt++)
        #pragma unroll
        for (int nt = 0; nt < 4; nt++)
            #pragma unroll
            for (int e = 0; e < 4; e++) C[mt][nt][e] = 0.f;

    #pragma unroll
    for (int kc = 0; kc < 8; kc++) {
        uint32_t ah[2][4], al[2][4], bh[2][4], bl[2][4];
        #pragma unroll
        for (int mt = 0; mt < 2; mt++) {
            uint32_t o = mt * (16 * STRIDE_B) + kc * 32;
            LDSM4(ah[mt], aHiB + o);
            LDSM4(al[mt], aLoB + o);
        }
        #pragma unroll
        for (int ng = 0; ng < 2; ng++) {
            uint32_t o = ng * (16 * STRIDE_B) + kc * 32;
            LDSM4(bh[ng], bHiB + o);
            LDSM4(bl[ng], bLoB + o);
        }
        // pass 1: hi*hi — 8 distinct C fragments
        #pragma unroll
        for (int mt = 0; mt < 2; mt++)
            #pragma unroll
            for (int ng = 0; ng < 2; ng++) {
                MMA_BF16(C[mt][2 * ng],     ah[mt], bh[ng][0], bh[ng][1]);
                MMA_BF16(C[mt][2 * ng + 1], ah[mt], bh[ng][2], bh[ng][3]);
            }
        // pass 2: hi*lo
        #pragma unroll
        for (int mt = 0; mt < 2; mt++)
            #pragma unroll
            for (int ng = 0; ng < 2; ng++) {
                MMA_BF16(C[mt][2 * ng],     ah[mt], bl[ng][0], bl[ng][1]);
                MMA_BF16(C[mt][2 * ng + 1], ah[mt], bl[ng][2], bl[ng][3]);
            }
        // pass 3: lo*hi
        #pragma unroll
        for (int mt = 0; mt < 2; mt++)
            #pragma unroll
            for (int ng = 0; ng < 2; ng++) {
                MMA_BF16(C[mt][2 * ng],     al[mt], bh[ng][0], bh[ng][1]);
                MMA_BF16(C[mt][2 * ng + 1], al[mt], bh[ng][2], bh[ng][3]);
            }
    }
}

// ---------------- epilogue on C fragments, q read from smem stage ----------
__device__ __forceinline__ void epi_tile(const float (&C)[2][4][4],
    const float* sPq, int wc, int qe,
    const float (&pix)[4], const float (&piy)[4], const float (&piz)[4],
    float (&ax)[4], float (&ay)[4], float (&az)[4])
{
    float qx[8], qy[8], qz[8];
    #pragma unroll
    for (int nt = 0; nt < 4; nt++)
        #pragma unroll
        for (int e = 0; e < 2; e++) {
            int col = 32 * wc + 8 * nt + 2 * qe + e;
            qx[2 * nt + e] = sPq[col * 3 + 0];
            qy[2 * nt + e] = sPq[col * 3 + 1];
            qz[2 * nt + e] = sPq[col * 3 + 2];
        }
    #pragma unroll
    for (int mt = 0; mt < 2; mt++)
        #pragma unroll
        for (int h = 0; h < 2; h++) {
            int ridx = 2 * mt + h;
            float px = pix[ridx], py = piy[ridx], pz = piz[ridx];
            #pragma unroll
            for (int nt = 0; nt < 4; nt++)
                #pragma unroll
                for (int e = 0; e < 2; e++) {
                    int cidx = 2 * nt + e;
                    float dx = px - qx[cidx];
                    float dy = py - qy[cidx];
                    float dz = pz - qz[cidx];
                    float d2 = fmaf(dx, dx, fmaf(dy, dy, dz * dz));
                    float inv = rsqrtf(fmaxf(d2, 1e-36f)); // diag -> 0
                    float w = C[mt][nt][2 * h + e] * inv;
                    ax[ridx] = fmaf(w, dx, ax[ridx]);
                    ay[ridx] = fmaf(w, dy, ay[ridx]);
                    az[ridx] = fmaf(w, dz, az[ridx]);
                }
        }
}

// ---------------- refill: async-load tile jn into B buffers + pos stage ----
__device__ __forceinline__ void issue_refill(uint32_t sb, int tid, int b, int jn,
                                             uint32_t bhiOff, uint32_t bloOff,
                                             const float* pb)
{
    const uint32_t* bh = g_vhi + ((size_t)b * NATOMS + jn) * 64;
    const uint32_t* bl = g_vlo + ((size_t)b * NATOMS + jn) * 64;
    #pragma unroll
    for (int it = 0; it < 4; it++) {
        int idx = tid + it * THREADS;
        int r = idx >> 4, c = idx & 15;
        cpa16(sb + bhiOff + r * STRIDE_B + c * 16, bh + r * 64 + c * 4);
        cpa16(sb + bloOff + r * STRIDE_B + c * 16, bl + r * 64 + c * 4);
    }
    if (tid < 384) {
        int stage = (jn / TJ) & 3;
        cpa4(sb + OFF_PQ + stage * 1536 + tid * 4, pb + jn * 3 + tid);
    }
    CP_COMMIT();
}

// ---------------- main kernel ----------------------------------------------
__global__ __launch_bounds__(THREADS, 1)
void gen_actions_kernel(const float* __restrict__ pos,
                        const float* __restrict__ mask,
                        const float* __restrict__ ascale,
                        float* __restrict__ out)
{
    extern __shared__ char sp[];
    const uint32_t sb = smem_u32(sp);

    const int tid  = threadIdx.x;
    const int wid  = tid >> 5;
    const int lane = tid & 31;
    const int wr   = wid & 3;       // warp row: S rows [32wr, 32wr+32)
    const int wc   = wid >> 2;      // warp col: S cols [32wc, 32wc+32)
    const int qid  = lane >> 2;
    const int qe   = lane & 3;

    const int b  = blockIdx.y;
    const int i0 = blockIdx.x * TI;

    const float* mb = mask + (size_t)b * NATOMS;
    const float* pb = pos  + (size_t)b * NATOMS * 3;

    // ---- prologue: A tiles + B tile 0 + pos stage 0, ONE group ----
    {
        const uint32_t* ah = g_khi + ((size_t)b * NATOMS + i0) * 64;
        const uint32_t* al = g_klo + ((size_t)b * NATOMS + i0) * 64;
        const uint32_t* bh = g_vhi + (size_t)b * NATOMS * 64;   // jt = 0
        const uint32_t* bl = g_vlo + (size_t)b * NATOMS * 64;
        #pragma unroll
        for (int it = 0; it < 4; it++) {
            int idx = tid + it * THREADS;
            int r = idx >> 4, c = idx & 15;
            cpa16(sb + OFF_AHI  + r * STRIDE_B + c * 16, ah + r * 64 + c * 4);
            cpa16(sb + OFF_ALO  + r * STRIDE_B + c * 16, al + r * 64 + c * 4);
            cpa16(sb + OFF_BHI0 + r * STRIDE_B + c * 16, bh + r * 64 + c * 4);
            cpa16(sb + OFF_BLO0 + r * STRIDE_B + c * 16, bl + r * 64 + c * 4);
        }
        if (tid < 384) cpa4(sb + OFF_PQ + tid * 4, pb + tid);
        CP_COMMIT();
    }

    // ---- mask sum (overlaps the async loads) ----
    {
        float* sMS = (float*)(sp + OFF_MS);
        float ms = 0.f;
        for (int n = tid; n < NATOMS; n += THREADS) ms += mb[n];
        #pragma unroll
        for (int off = 16; off > 0; off >>= 1)
            ms += __shfl_xor_sync(0xFFFFFFFFu, ms, off);
        if (lane == 0) sMS[wid] = ms;
    }
    __syncthreads();
    float msum = 0.f;
    {
        float* sMS = (float*)(sp + OFF_MS);
        #pragma unroll
        for (int q = 0; q < 16; q++) msum += sMS[q];
    }
    const float inv_msum = 1.0f / msum;
    const float as = ascale[0];

    // ---- this thread's 4 fixed rows: 32wr + 16mt + 8h + qid ----
    float pix[4], piy[4], piz[4];
    #pragma unroll
    for (int mt = 0; mt < 2; mt++)
        #pragma unroll
        for (int h = 0; h < 2; h++) {
            int gi = i0 + 32 * wr + 16 * mt + 8 * h + qid;
            const float* p = pb + (size_t)gi * 3;
            pix[2 * mt + h] = p[0]; piy[2 * mt + h] = p[1]; piz[2 * mt + h] = p[2];
        }

    // ---- ldmatrix lane base addresses (conflict-free) ----
    const uint32_t aRow = 32 * wr + (lane & 15);
    const uint32_t aKof = (lane & 16) ? 16u : 0u;
    const uint32_t aHiB = sb + OFF_AHI + aRow * STRIDE_B + aKof;
    const uint32_t aLoB = sb + OFF_ALO + aRow * STRIDE_B + aKof;
    const uint32_t bRow = 32 * wc + (lane & 7) + ((lane & 16) ? 8 : 0);
    const uint32_t bKof = (lane & 8) ? 16u : 0u;
    const uint32_t bLaneOff = bRow * STRIDE_B + bKof;

    float ax[4], ay[4], az[4];
    #pragma unroll
    for (int r = 0; r < 4; r++) { ax[r] = 0.f; ay[r] = 0.f; az[r] = 0.f; }

    float C[2][4][4];
    const float* sPqBase = (const float*)(sp + OFF_PQ);

    for (int t = 0; t < 8; t++) {
        CP_WAIT0();
        __syncthreads();
        if (t < 7)
            issue_refill(sb, tid, b, (t + 1) * TJ,
                         ((t + 1) & 1) ? OFF_BHI1 : OFF_BHI0,
                         ((t + 1) & 1) ? OFF_BLO1 : OFF_BLO0, pb);
        const uint32_t bhiC = (t & 1) ? OFF_BHI1 : OFF_BHI0;
        const uint32_t bloC = (t & 1) ? OFF_BLO1 : OFF_BLO0;
        gemm_tile(C, aHiB, aLoB, sb + bhiC + bLaneOff, sb + bloC + bLaneOff);
        epi_tile(C, sPqBase + (t & 3) * 384, wc, qe, pix, piy, piz, ax, ay, az);
    }

    // ---- reduce over quad lanes (same rows, different cols) ----
    #pragma unroll
    for (int off = 1; off < 4; off <<= 1)
        #pragma unroll
        for (int r = 0; r < 4; r++) {
            ax[r] += __shfl_xor_sync(0xFFFFFFFFu, ax[r], off);
            ay[r] += __shfl_xor_sync(0xFFFFFFFFu, ay[r], off);
            az[r] += __shfl_xor_sync(0xFFFFFFFFu, az[r], off);
        }

    __syncthreads();
    float* sRed = (float*)(sp + OFF_RED);    // [4 col-groups][128 rows][3]
    if (qe == 0) {
        #pragma unroll
        for (int mt = 0; mt < 2; mt++)
            #pragma unroll
            for (int h = 0; h < 2; h++) {
                int row = 32 * wr + 16 * mt + 8 * h + qid;
                float* d = sRed + (wc * 128 + row) * 3;
                int ridx = 2 * mt + h;
                d[0] = ax[ridx]; d[1] = ay[ridx]; d[2] = az[ridx];
            }
    }
    __syncthreads();

    if (tid < TI) {
        int gi = i0 + tid;
        float sx = 0.f, sy = 0.f, sz = 0.f;
        #pragma unroll
        for (int g = 0; g < 4; g++) {
            const float* d = sRed + (g * 128 + tid) * 3;
            sx += d[0]; sy += d[1]; sz += d[2];
        }
        float s = as * mb[gi];
        float* o = out + ((size_t)b * NATOMS + gi) * 3;
        o[0] = tanhf(sx * inv_msum) * s;
        o[1] = tanhf(sy * inv_msum) * s;
        o[2] = tanhf(sz * inv_msum) * s;
    }
}

extern "C" void kernel_launch(void* const* d_in, const int* in_sizes, int n_in,
                              void* d_out, int out_size) {
    const float* kv   = (const float*)d_in[0];
    const float* pos  = (const float*)d_in[1];
    const float* mask = (const float*)d_in[2];
    const float* asc  = (const float*)d_in[3];
    float* out = (float*)d_out;

    cudaFuncSetAttribute(gen_actions_kernel,
                         cudaFuncAttributeMaxDynamicSharedMemorySize,
                         (int)SMEM_BYTES);

    split_kv_kernel<<<(BATCH * NATOMS * 64 + 255) / 256, 256>>>(kv, mask);

    dim3 grid(NATOMS / TI, BATCH);   // 8 x 16 = 128 blocks, one wave
    gen_actions_kernel<<<grid, THREADS, SMEM_BYTES>>>(pos, mask, asc, out);
}